// round 13
// baseline (speedup 1.0000x reference)
#include <cuda_runtime.h>
#include <math.h>

// Problem constants (shapes fixed by the dataset)
#define NB 32
#define NA 3
#define NH 128
#define NW 128
#define NCH (NA * 6)              // 18 channels
#define NPLANE (NH * NW)          // 16384
#define NCELL (NB * NA * NPLANE)  // 1,572,864
#define EPSF 1e-7f
#define NEG_LOG_EPS 16.118095651f // -log(1e-7), the BCE clamp ceiling
#define DENSE_BLOCKS 1536         // 1536 x 256 x 1 float4 = 393216 exactly

// Self-cleaning scratch (zero-initialized at module load; every launch restores zeros)
__device__ int    d_clr[NCELL];    // cleared-cell dedup flags
__device__ int    d_owner[NCELL];  // winning gt index + 1 per obj cell
__device__ double d_total;         // dense noobj-BCE sum over ALL cells
__device__ double d_corr;          // correction sum (noobj terms at cleared cells)
__device__ double d_obj;           // obj BCE + bbox loss sum (takeover-telescoped)
__device__ int    d_nclr;          // # distinct cleared cells
__device__ int    d_nobj;          // # distinct obj cells
__device__ int    d_doneGT;        // GT-block completion count   (RED-incremented)
__device__ int    d_doneDense;     // dense-block completion count (RED-incremented)

__constant__ float c_aw[3] = {116.f, 156.f, 373.f};
__constant__ float c_ah[3] = { 90.f, 198.f, 326.f};

// precise variants (sparse path, few thousand evals)
__device__ __forceinline__ float bce_neg(float v) {
    float s = 1.0f / (1.0f + expf(-v));
    float p = fminf(fmaxf(s, EPSF), 1.0f - EPSF);
    return -logf(1.0f - p);
}
__device__ __forceinline__ float bce_pos(float v) {
    float s = 1.0f / (1.0f + expf(-v));
    float p = fminf(fmaxf(s, EPSF), 1.0f - EPSF);
    return -logf(p);
}
__device__ __forceinline__ float sigmoidf_(float v) {
    return 1.0f / (1.0f + expf(-v));
}
// dense path: -log(1 - clip(sigmoid(v))) == min(softplus(v), -log(eps)); 2 MUFU.
__device__ __forceinline__ float softplus_fast(float v) {
    float sp = __logf(1.0f + __expf(-fabsf(v))) + fmaxf(v, 0.0f);
    return fminf(sp, NEG_LOG_EPS);
}

// anchor IoUs + argmax for one gt box (grid units)
__device__ __forceinline__ int best_anchor(float gw, float gh,
                                           const float* awf, const float* ahf,
                                           float* ious) {
    float best = -1.0f; int bestn = 0;
#pragma unroll
    for (int a = 0; a < 3; a++) {
        float inter = fminf(gw, awf[a]) * fminf(gh, ahf[a]);
        float uni   = gw * gh + awf[a] * ahf[a] - inter;
        float iou   = inter / uni;
        ious[a] = iou;
        if (iou > best) { best = iou; bestn = a; }
    }
    return bestn;
}

__device__ __forceinline__ double warp_reduce_d(double v) {
#pragma unroll
    for (int o = 16; o > 0; o >>= 1) v += __shfl_down_sync(0xffffffffu, v, o);
    return v;
}
__device__ __forceinline__ int warp_reduce_i(int v) {
#pragma unroll
    for (int o = 16; o > 0; o >>= 1) v += __shfl_down_sync(0xffffffffu, v, o);
    return v;
}

// Obj term for one (cell, gt-box) pair. __noinline__ so both call sites
// (adder and subtractor) execute identical code -> exact double telescoping.
__device__ __noinline__ double obj_term(const float* __restrict__ out,
                                        int b, int bestn, int gi, int gj,
                                        float gx, float gy, float gw, float gh,
                                        float aw, float ah) {
    const size_t base = (size_t)(b * NCH + bestn * 6) * NPLANE + gj * NW + gi;
    float p0 = out[base];
    float p1 = out[base + NPLANE];
    float p2 = out[base + 2 * NPLANE];
    float p3 = out[base + 3 * NPLANE];
    float p4 = out[base + 4 * NPLANE];
    float tx = gx - floorf(gx);
    float ty = gy - floorf(gy);
    float tw = logf(gw / aw);
    float th = logf(gh / ah);
    float xs = sigmoidf_(p0), ys = sigmoidf_(p1);
    float bb = (xs - tx) * (xs - tx) + (ys - ty) * (ys - ty)
             + (p2 - tw) * (p2 - tw) + (p3 - th) * (p3 - th);
    return (double)(bb + bce_pos(p4));   // OBJ_SCALE = 1
}

// ---------------------------------------------------------------------------
// Single kernel.
//   bid == 0                  : coordinator (poll GT done -> cleanup;
//                               poll dense done -> finalize + reset)
//   bid in [1, 1+gtABlocks)   : GT phase, one (gt, anchor) pair per thread
//   bid in [1+gtABlocks, ...) : dense conf-BCE sum (1 float4/thread)
// ALL block-completion signaling is non-returning RED atomics; only the
// coordinator's single polling thread issues returning atomics.
// ---------------------------------------------------------------------------
__global__ void yolo_loss_all(const float* __restrict__ out,
                              const int*   __restrict__ gt_batch,
                              const float* __restrict__ gt_boxes,
                              const int*   __restrict__ size_h,
                              const int*   __restrict__ size_w,
                              float* __restrict__ d_out,
                              int nGts, int gtABlocks) {
    const int tid  = threadIdx.x;
    const int bid  = blockIdx.x;
    const int lane = tid & 31;
    const int wid  = tid >> 5;

    __shared__ double sredD[8];
    __shared__ int    sredI[8];

    if (bid == 0) {
        // ======================= coordinator =======================
        const float stride_h = (float)((*size_h) / NH);
        const float stride_w = (float)((*size_w) / NW);
        float awf[3], ahf[3];
#pragma unroll
        for (int a = 0; a < 3; a++) { awf[a] = c_aw[a] / stride_w; ahf[a] = c_ah[a] / stride_h; }

        // wait for all GT blocks (few returning atomics from ONE thread only)
        if (tid == 0) {
            while (atomicAdd(&d_doneGT, 0) < gtABlocks) { __nanosleep(64); }
        }
        __syncthreads();
        __threadfence();   // acquire GT blocks' scratch writes

        // cleanup: zero every touched d_clr / d_owner cell
        for (int pair = tid; pair < 3 * nGts; pair += 256) {
            const int g = pair / 3;
            const int a = pair - 3 * g;
            const int b = gt_batch[g];
            float4 box = ((const float4*)gt_boxes)[g];
            float gw = box.z * (float)NW, gh = box.w * (float)NH;
            int gi = (int)(box.x * (float)NW), gj = (int)(box.y * (float)NH);

            float ious[3];
            int bestn = best_anchor(gw, gh, awf, ahf, ious);
            const int cellbase = ((b * NA) * NH + gj) * NW + gi;
            if ((ious[a] > 0.5f) || (a == bestn)) d_clr[cellbase + a * NPLANE] = 0;
            if (a == bestn) d_owner[cellbase + bestn * NPLANE] = 0;
        }

        // wait for all dense blocks, then finalize + reset
        if (tid == 0) {
            while (atomicAdd(&d_doneDense, 0) < DENSE_BLOCKS) { __nanosleep(64); }
            __threadfence();   // acquire dense blocks' d_total REDs
            double total = d_total;
            double corr  = d_corr;
            double obj   = d_obj;
            int    no    = d_nobj;
            int    ncl   = d_nclr;
            double n_obj  = (double)(no > 0 ? no : 1);
            int    nno    = NCELL - ncl;
            double n_noob = (double)(nno > 0 ? nno : 1);
            d_out[0] = (float)(obj / n_obj + 100.0 * (total - corr) / n_noob);
            // reset accumulators + tickets for the next launch (self-cleaning)
            d_total = 0.0; d_corr = 0.0; d_obj = 0.0;
            d_nclr = 0; d_nobj = 0; d_doneGT = 0; d_doneDense = 0;
        }
        return;
    }

    if (bid >= 1 + gtABlocks) {
        // ======================= dense conf-BCE sum =======================
        const int idx = (bid - 1 - gtABlocks) * 256 + tid;   // 0 .. 393215
        const float4* __restrict__ o4 = (const float4*)out;
        const int plane = idx >> 12;                         // 0..95  (b*3 + a)
        const int j     = idx & 4095;
        const int b     = plane / 3;
        const int a     = plane - 3 * b;
        float4 v = o4[(size_t)(b * NCH + a * 6 + 4) * 4096 + j];
        float s = softplus_fast(v.x) + softplus_fast(v.y)
                + softplus_fast(v.z) + softplus_fast(v.w);

        double ds = warp_reduce_d((double)s);
        if (lane == 0) sredD[wid] = ds;
        __syncthreads();
        if (wid == 0) {
            double t = (lane < 8) ? sredD[lane] : 0.0;
#pragma unroll
            for (int o = 4; o > 0; o >>= 1) t += __shfl_down_sync(0xffu, t, o);
            if (lane == 0) {
                atomicAdd(&d_total, t);        // non-returning -> REDG
                __threadfence();               // order d_total before ticket
                atomicAdd(&d_doneDense, 1);    // non-returning -> REDG
            }
        }
        return;
    }

    // ======================= GT phase: one (gt, anchor) pair per thread ======
    const float stride_h = (float)((*size_h) / NH);
    const float stride_w = (float)((*size_w) / NW);
    float awf[3], ahf[3];
#pragma unroll
    for (int a = 0; a < 3; a++) { awf[a] = c_aw[a] / stride_w; ahf[a] = c_ah[a] / stride_h; }

    const int pair = (bid - 1) * 256 + tid;                // 0 .. 3*nGts-1
    double corr = 0.0, objsum = 0.0;
    int nclr = 0, nobj = 0;
    if (pair < 3 * nGts) {
        const int g = pair / 3;
        const int a = pair - 3 * g;
        const int b = gt_batch[g];
        float4 box = ((const float4*)gt_boxes)[g];
        float gx = box.x * (float)NW, gy = box.y * (float)NH;
        float gw = box.z * (float)NW, gh = box.w * (float)NH;
        int gi = (int)gx, gj = (int)gy;

        float ious[3];
        int bestn = best_anchor(gw, gh, awf, ahf, ious);
        const int cellbase = ((b * NA) * NH + gj) * NW + gi;

        // this thread's anchor clear + correction term
        if ((ious[a] > 0.5f) || (a == bestn)) {
            int cell = cellbase + a * NPLANE;
            if (atomicExch(&d_clr[cell], 1) == 0) {
                float v = out[(size_t)(b * NCH + a * 6 + 4) * NPLANE + gj * NW + gi];
                corr += (double)bce_neg(v);
                nclr++;
            }
        }

        // owner takeover accounting (telescopes to final winner's term)
        if (a == bestn) {
            const int cell = cellbase + bestn * NPLANE;
            int old = atomicMax(&d_owner[cell], g + 1);
            if (old < g + 1) {
                objsum += obj_term(out, b, bestn, gi, gj, gx, gy, gw, gh,
                                   awf[bestn], ahf[bestn]);
                if (old == 0) {
                    nobj++;
                } else {
                    // displaced gt old-1 maps to the SAME cell
                    float4 obox = ((const float4*)gt_boxes)[old - 1];
                    float ogx = obox.x * (float)NW, ogy = obox.y * (float)NH;
                    float ogw = obox.z * (float)NW, ogh = obox.w * (float)NH;
                    objsum -= obj_term(out, b, bestn, gi, gj, ogx, ogy, ogw, ogh,
                                       awf[bestn], ahf[bestn]);
                }
            }
        }
    }

    double dsC = warp_reduce_d(corr);
    double dsO = warp_reduce_d(objsum);
    int    isC = warp_reduce_i(nclr);
    int    isO = warp_reduce_i(nobj);
    if (lane == 0) { sredD[wid] = dsC; sredI[wid] = isC; }
    __syncthreads();   // also: all returning scratch atomics above have completed
    if (wid == 0) {
        double sC = (lane < 8) ? sredD[lane] : 0.0;
        int    nC = (lane < 8) ? sredI[lane] : 0;
#pragma unroll
        for (int o = 4; o > 0; o >>= 1) {
            sC += __shfl_down_sync(0xffu, sC, o);
            nC += __shfl_down_sync(0xffu, nC, o);
        }
        if (lane == 0 && nC > 0) { atomicAdd(&d_corr, sC); atomicAdd(&d_nclr, nC); }
    }
    __syncthreads();
    if (lane == 0) { sredD[wid] = dsO; sredI[wid] = isO; }
    __syncthreads();
    if (wid == 0) {
        double sO = (lane < 8) ? sredD[lane] : 0.0;
        int    nO = (lane < 8) ? sredI[lane] : 0;
#pragma unroll
        for (int o = 4; o > 0; o >>= 1) {
            sO += __shfl_down_sync(0xffu, sO, o);
            nO += __shfl_down_sync(0xffu, nO, o);
        }
        if (lane == 0) {
            if (sO != 0.0) atomicAdd(&d_obj, sO);
            if (nO > 0)    atomicAdd(&d_nobj, nO);
            __threadfence();              // order accumulators + scratch before ticket
            atomicAdd(&d_doneGT, 1);      // non-returning -> REDG
        }
    }
}

extern "C" void kernel_launch(void* const* d_in, const int* in_sizes, int n_in,
                              void* d_out, int out_size) {
    const float* out      = (const float*)d_in[0];
    const int*   gt_batch = (const int*)  d_in[1];
    const float* gt_boxes = (const float*)d_in[2];
    const int*   size_h   = (const int*)  d_in[3];
    const int*   size_w   = (const int*)  d_in[4];
    float* outp = (float*)d_out;
    const int nGts = in_sizes[1];

    const int gtABlocks = (3 * nGts + 255) / 256;     // 23 for nGts=1920
    const int grid = 1 + gtABlocks + DENSE_BLOCKS;    // 1560 blocks
    yolo_loss_all<<<grid, 256>>>(out, gt_batch, gt_boxes,
                                 size_h, size_w, outp, nGts, gtABlocks);
}

// round 15
// speedup vs baseline: 1.7975x; 1.7975x over previous
#include <cuda_runtime.h>
#include <math.h>

// Problem constants (shapes fixed by the dataset)
#define NB 32
#define NA 3
#define NH 128
#define NW 128
#define NCH (NA * 6)              // 18 channels
#define NPLANE (NH * NW)          // 16384
#define NCELL (NB * NA * NPLANE)  // 1,572,864
#define EPSF 1e-7f
#define NEG_LOG_EPS 16.118095651f // -log(1e-7), the BCE clamp ceiling
#define DB 384                    // dense blocks
#define DWORK 4                   // float4 per dense thread; DB*256*DWORK = 393216

// Generation-tagged scratch: tag = (gen << 32) | (g+1 for owner, 0 for clear-only).
// Entries from previous launches have a smaller gen -> automatically stale.
// NO cleanup pass is ever needed.
__device__ unsigned long long d_tag[NCELL];
__device__ unsigned int d_gen;     // bumped once per launch, at end of finalize
__device__ double d_total;         // dense noobj-BCE sum over ALL cells
__device__ double d_corr;          // correction sum (noobj terms at cleared cells)
__device__ double d_obj;           // obj BCE + bbox loss sum (takeover-telescoped)
__device__ int    d_nclr;          // # distinct cleared cells
__device__ int    d_nobj;          // # distinct obj cells

__constant__ float c_aw[3] = {116.f, 156.f, 373.f};
__constant__ float c_ah[3] = { 90.f, 198.f, 326.f};

// precise variants (sparse path, few thousand evals)
__device__ __forceinline__ float bce_neg(float v) {
    float s = 1.0f / (1.0f + expf(-v));
    float p = fminf(fmaxf(s, EPSF), 1.0f - EPSF);
    return -logf(1.0f - p);
}
__device__ __forceinline__ float bce_pos(float v) {
    float s = 1.0f / (1.0f + expf(-v));
    float p = fminf(fmaxf(s, EPSF), 1.0f - EPSF);
    return -logf(p);
}
__device__ __forceinline__ float sigmoidf_(float v) {
    return 1.0f / (1.0f + expf(-v));
}
// dense path: -log(1 - clip(sigmoid(v))) == min(softplus(v), -log(eps)); 2 MUFU.
__device__ __forceinline__ float softplus_fast(float v) {
    float sp = __logf(1.0f + __expf(-fabsf(v))) + fmaxf(v, 0.0f);
    return fminf(sp, NEG_LOG_EPS);
}

// anchor IoUs + argmax for one gt box (grid units)
__device__ __forceinline__ int best_anchor(float gw, float gh,
                                           const float* awf, const float* ahf,
                                           float* ious) {
    float best = -1.0f; int bestn = 0;
#pragma unroll
    for (int a = 0; a < 3; a++) {
        float inter = fminf(gw, awf[a]) * fminf(gh, ahf[a]);
        float uni   = gw * gh + awf[a] * ahf[a] - inter;
        float iou   = inter / uni;
        ious[a] = iou;
        if (iou > best) { best = iou; bestn = a; }
    }
    return bestn;
}

__device__ __forceinline__ double warp_reduce_d(double v) {
#pragma unroll
    for (int o = 16; o > 0; o >>= 1) v += __shfl_down_sync(0xffffffffu, v, o);
    return v;
}
__device__ __forceinline__ int warp_reduce_i(int v) {
#pragma unroll
    for (int o = 16; o > 0; o >>= 1) v += __shfl_down_sync(0xffffffffu, v, o);
    return v;
}

// Obj term for one (cell, gt-box) pair. __noinline__ so both call sites
// (adder and subtractor) execute identical code -> exact double telescoping.
__device__ __noinline__ double obj_term(const float* __restrict__ out,
                                        int b, int bestn, int gi, int gj,
                                        float gx, float gy, float gw, float gh,
                                        float aw, float ah) {
    const size_t base = (size_t)(b * NCH + bestn * 6) * NPLANE + gj * NW + gi;
    float p0 = out[base];
    float p1 = out[base + NPLANE];
    float p2 = out[base + 2 * NPLANE];
    float p3 = out[base + 3 * NPLANE];
    float p4 = out[base + 4 * NPLANE];
    float tx = gx - floorf(gx);
    float ty = gy - floorf(gy);
    float tw = logf(gw / aw);
    float th = logf(gh / ah);
    float xs = sigmoidf_(p0), ys = sigmoidf_(p1);
    float bb = (xs - tx) * (xs - tx) + (ys - ty) * (ys - ty)
             + (p2 - tw) * (p2 - tw) + (p3 - th) * (p3 - th);
    return (double)(bb + bce_pos(p4));   // OBJ_SCALE = 1
}

// ---------------------------------------------------------------------------
// K1: blocks [0, gtABlocks)       : GT phase, one (gt, anchor) pair per thread,
//                                   ONE atomicMax on the gen-tagged scratch.
//     blocks [gtABlocks, +DB)     : dense conf-BCE sum (4 float4/thread).
// All blocks fully independent; accumulators via non-returning RED atomics.
// ---------------------------------------------------------------------------
__global__ void k1_dense_gt(const float* __restrict__ out,
                            const int*   __restrict__ gt_batch,
                            const float* __restrict__ gt_boxes,
                            const int*   __restrict__ size_h,
                            const int*   __restrict__ size_w,
                            int nGts, int gtABlocks) {
    const int tid  = threadIdx.x;
    const int bid  = blockIdx.x;
    const int lane = tid & 31;
    const int wid  = tid >> 5;

    __shared__ double sredD[8];
    __shared__ int    sredI[8];

    if (bid >= gtABlocks) {
        // ---------------- dense conf-BCE sum ----------------
        const int t = (bid - gtABlocks) * 256 + tid;       // 0 .. 98303
        const float4* __restrict__ o4 = (const float4*)out;
        float acc = 0.0f;
#pragma unroll
        for (int k = 0; k < DWORK; k++) {
            const int idx   = t + k * (DB * 256);          // 0 .. 393215
            const int plane = idx >> 12;                   // 0..95  (b*3 + a)
            const int j     = idx & 4095;
            const int b     = plane / 3;
            const int a     = plane - 3 * b;
            float4 v = o4[(size_t)(b * NCH + a * 6 + 4) * 4096 + j];
            acc += softplus_fast(v.x) + softplus_fast(v.y)
                 + softplus_fast(v.z) + softplus_fast(v.w);
        }
        double ds = warp_reduce_d((double)acc);
        if (lane == 0) sredD[wid] = ds;
        __syncthreads();
        if (wid == 0) {
            double s = (lane < 8) ? sredD[lane] : 0.0;
#pragma unroll
            for (int o = 4; o > 0; o >>= 1) s += __shfl_down_sync(0xffu, s, o);
            if (lane == 0) atomicAdd(&d_total, s);         // non-returning -> RED
        }
        return;
    }

    // ---------------- GT phase: one (gt, anchor) pair per thread --------------
    const unsigned int gen = d_gen + 1;   // stable for the whole launch
    const float stride_h = (float)((*size_h) / NH);
    const float stride_w = (float)((*size_w) / NW);
    float awf[3], ahf[3];
#pragma unroll
    for (int a = 0; a < 3; a++) { awf[a] = c_aw[a] / stride_w; ahf[a] = c_ah[a] / stride_h; }

    const int pair = bid * 256 + tid;                      // 0 .. 3*nGts-1
    double corr = 0.0, objsum = 0.0;
    int nclr = 0, nobj = 0;
    if (pair < 3 * nGts) {
        const int g = pair / 3;
        const int a = pair - 3 * g;
        const int b = gt_batch[g];
        float4 box = ((const float4*)gt_boxes)[g];
        float gx = box.x * (float)NW, gy = box.y * (float)NH;
        float gw = box.z * (float)NW, gh = box.w * (float)NH;
        int gi = (int)gx, gj = (int)gy;

        float ious[3];
        int bestn = best_anchor(gw, gh, awf, ahf, ious);
        const bool isbest  = (a == bestn);
        const bool cleared = (ious[a] > 0.5f) || isbest;

        if (cleared) {
            const int cell = ((b * NA + a) * NH + gj) * NW + gi;
            const unsigned long long newv =
                ((unsigned long long)gen << 32) | (isbest ? (unsigned)(g + 1) : 0u);
            unsigned long long old = atomicMax(&d_tag[cell], newv);
            const unsigned int old_gen = (unsigned int)(old >> 32);
            const unsigned int old_g   = (unsigned int)old;   // g+1 of prior owner (this gen)
            const bool first = (old_gen < gen);

            if (first) {   // first toucher of this cell this launch -> noobj correction
                float v = out[(size_t)(b * NCH + a * 6 + 4) * NPLANE + gj * NW + gi];
                corr += (double)bce_neg(v);
                nclr++;
            }
            if (isbest) {
                const unsigned int prior = first ? 0u : old_g;
                if (prior < (unsigned)(g + 1)) {   // we became the (transient) owner
                    objsum += obj_term(out, b, bestn, gi, gj, gx, gy, gw, gh,
                                       awf[bestn], ahf[bestn]);
                    if (prior == 0u) {
                        nobj++;
                    } else {
                        // displaced gt prior-1 maps to the SAME cell
                        float4 obox = ((const float4*)gt_boxes)[prior - 1];
                        float ogx = obox.x * (float)NW, ogy = obox.y * (float)NH;
                        float ogw = obox.z * (float)NW, ogh = obox.w * (float)NH;
                        objsum -= obj_term(out, b, bestn, gi, gj, ogx, ogy, ogw, ogh,
                                           awf[bestn], ahf[bestn]);
                    }
                }
            }
        }
    }

    double dsC = warp_reduce_d(corr);
    double dsO = warp_reduce_d(objsum);
    int    isC = warp_reduce_i(nclr);
    int    isO = warp_reduce_i(nobj);
    if (lane == 0) { sredD[wid] = dsC; sredI[wid] = isC; }
    __syncthreads();
    if (wid == 0) {
        double s = (lane < 8) ? sredD[lane] : 0.0;
        int    n = (lane < 8) ? sredI[lane] : 0;
#pragma unroll
        for (int o = 4; o > 0; o >>= 1) {
            s += __shfl_down_sync(0xffu, s, o);
            n += __shfl_down_sync(0xffu, n, o);
        }
        if (lane == 0 && n > 0) { atomicAdd(&d_corr, s); atomicAdd(&d_nclr, n); }
    }
    __syncthreads();
    if (lane == 0) { sredD[wid] = dsO; sredI[wid] = isO; }
    __syncthreads();
    if (wid == 0) {
        double s = (lane < 8) ? sredD[lane] : 0.0;
        int    n = (lane < 8) ? sredI[lane] : 0;
#pragma unroll
        for (int o = 4; o > 0; o >>= 1) {
            s += __shfl_down_sync(0xffu, s, o);
            n += __shfl_down_sync(0xffu, n, o);
        }
        if (lane == 0) {
            if (s != 0.0) atomicAdd(&d_obj, s);
            if (n > 0)    atomicAdd(&d_nobj, n);
        }
    }
}

// ---------------------------------------------------------------------------
// K2: ONE tiny block — combine accumulators into the scalar, reset them,
// and bump the generation (which retires ALL scratch tags at zero cost).
// ---------------------------------------------------------------------------
__global__ void k2_finalize(float* __restrict__ d_out) {
    if (threadIdx.x == 0) {
        double total = d_total;
        double corr  = d_corr;
        double obj   = d_obj;
        int    no    = d_nobj;
        int    ncl   = d_nclr;
        double n_obj  = (double)(no > 0 ? no : 1);
        int    nno    = NCELL - ncl;
        double n_noob = (double)(nno > 0 ? nno : 1);
        d_out[0] = (float)(obj / n_obj + 100.0 * (total - corr) / n_noob);
        // reset accumulators; bump gen -> all d_tag entries become stale
        d_total = 0.0; d_corr = 0.0; d_obj = 0.0;
        d_nclr = 0; d_nobj = 0;
        d_gen = d_gen + 1;
    }
}

extern "C" void kernel_launch(void* const* d_in, const int* in_sizes, int n_in,
                              void* d_out, int out_size) {
    const float* out      = (const float*)d_in[0];
    const int*   gt_batch = (const int*)  d_in[1];
    const float* gt_boxes = (const float*)d_in[2];
    const int*   size_h   = (const int*)  d_in[3];
    const int*   size_w   = (const int*)  d_in[4];
    float* outp = (float*)d_out;
    const int nGts = in_sizes[1];

    const int gtABlocks = (3 * nGts + 255) / 256;   // 23 for nGts=1920
    k1_dense_gt<<<gtABlocks + DB, 256>>>(out, gt_batch, gt_boxes,
                                         size_h, size_w, nGts, gtABlocks);
    k2_finalize<<<1, 32>>>(outp);
}

// round 16
// speedup vs baseline: 2.1399x; 1.1905x over previous
#include <cuda_runtime.h>
#include <math.h>

// Problem constants (shapes fixed by the dataset)
#define NB 32
#define NA 3
#define NH 128
#define NW 128
#define NCH (NA * 6)              // 18 channels
#define NPLANE (NH * NW)          // 16384
#define NCELL (NB * NA * NPLANE)  // 1,572,864
#define EPSF 1e-7f
#define NEG_LOG_EPS 16.118095651f // -log(1e-7), the BCE clamp ceiling
#define DB 384                    // dense blocks
#define DWORK 4                   // float4 per dense thread; DB*256*DWORK = 393216

// Generation-tagged scratch: tag = (gen << 32) | (g+1 for owner, 0 for clear-only).
// Entries from previous launches have a smaller gen -> automatically stale.
// NO cleanup pass is ever needed.
__device__ unsigned long long d_tag[NCELL];
__device__ unsigned int d_gen;     // bumped once per launch, at end of finalize
__device__ double d_total;         // dense noobj-BCE sum over ALL cells
__device__ double d_corr;          // correction sum (noobj terms at cleared cells)
__device__ double d_obj;           // obj BCE + bbox loss sum (takeover-telescoped)
__device__ int    d_nclr;          // # distinct cleared cells
__device__ int    d_nobj;          // # distinct obj cells

__constant__ float c_aw[3] = {116.f, 156.f, 373.f};
__constant__ float c_ah[3] = { 90.f, 198.f, 326.f};

// precise variants (sparse path, few thousand evals)
__device__ __forceinline__ float bce_neg(float v) {
    float s = 1.0f / (1.0f + expf(-v));
    float p = fminf(fmaxf(s, EPSF), 1.0f - EPSF);
    return -logf(1.0f - p);
}
__device__ __forceinline__ float bce_pos(float v) {
    float s = 1.0f / (1.0f + expf(-v));
    float p = fminf(fmaxf(s, EPSF), 1.0f - EPSF);
    return -logf(p);
}
__device__ __forceinline__ float sigmoidf_(float v) {
    return 1.0f / (1.0f + expf(-v));
}
// dense path: -log(1 - clip(sigmoid(v))) == min(softplus(v), -log(eps)); 2 MUFU.
__device__ __forceinline__ float softplus_fast(float v) {
    float sp = __logf(1.0f + __expf(-fabsf(v))) + fmaxf(v, 0.0f);
    return fminf(sp, NEG_LOG_EPS);
}

// anchor IoUs + argmax for one gt box (grid units)
__device__ __forceinline__ int best_anchor(float gw, float gh,
                                           const float* awf, const float* ahf,
                                           float* ious) {
    float best = -1.0f; int bestn = 0;
#pragma unroll
    for (int a = 0; a < 3; a++) {
        float inter = fminf(gw, awf[a]) * fminf(gh, ahf[a]);
        float uni   = gw * gh + awf[a] * ahf[a] - inter;
        float iou   = inter / uni;
        ious[a] = iou;
        if (iou > best) { best = iou; bestn = a; }
    }
    return bestn;
}

__device__ __forceinline__ double warp_reduce_d(double v) {
#pragma unroll
    for (int o = 16; o > 0; o >>= 1) v += __shfl_down_sync(0xffffffffu, v, o);
    return v;
}
__device__ __forceinline__ int warp_reduce_i(int v) {
#pragma unroll
    for (int o = 16; o > 0; o >>= 1) v += __shfl_down_sync(0xffffffffu, v, o);
    return v;
}

// Obj term for one (cell, gt-box) pair. __noinline__ so both call sites
// (adder and subtractor) execute identical code -> exact double telescoping.
__device__ __noinline__ double obj_term(const float* __restrict__ out,
                                        int b, int bestn, int gi, int gj,
                                        float gx, float gy, float gw, float gh,
                                        float aw, float ah) {
    const size_t base = (size_t)(b * NCH + bestn * 6) * NPLANE + gj * NW + gi;
    float p0 = out[base];
    float p1 = out[base + NPLANE];
    float p2 = out[base + 2 * NPLANE];
    float p3 = out[base + 3 * NPLANE];
    float p4 = out[base + 4 * NPLANE];
    float tx = gx - floorf(gx);
    float ty = gy - floorf(gy);
    float tw = logf(gw / aw);
    float th = logf(gh / ah);
    float xs = sigmoidf_(p0), ys = sigmoidf_(p1);
    float bb = (xs - tx) * (xs - tx) + (ys - ty) * (ys - ty)
             + (p2 - tw) * (p2 - tw) + (p3 - th) * (p3 - th);
    return (double)(bb + bce_pos(p4));   // OBJ_SCALE = 1
}

// ---------------------------------------------------------------------------
// K1: blocks [0, gtABlocks)       : GT phase, one (gt, anchor) pair per thread,
//                                   ONE atomicMax on the gen-tagged scratch.
//     blocks [gtABlocks, +DB)     : dense conf-BCE sum (4 float4/thread).
// All blocks fully independent; accumulators via non-returning RED atomics.
// Each block triggers programmatic launch completion immediately: K2's
// prologue overlaps K1; K2's grid-dependency-sync provides the memory fence.
// ---------------------------------------------------------------------------
__global__ void k1_dense_gt(const float* __restrict__ out,
                            const int*   __restrict__ gt_batch,
                            const float* __restrict__ gt_boxes,
                            const int*   __restrict__ size_h,
                            const int*   __restrict__ size_w,
                            int nGts, int gtABlocks) {
    cudaTriggerProgrammaticLaunchCompletion();   // let K2's prologue start now

    const int tid  = threadIdx.x;
    const int bid  = blockIdx.x;
    const int lane = tid & 31;
    const int wid  = tid >> 5;

    __shared__ double sredD[8];
    __shared__ int    sredI[8];

    if (bid >= gtABlocks) {
        // ---------------- dense conf-BCE sum ----------------
        const int t = (bid - gtABlocks) * 256 + tid;       // 0 .. 98303
        const float4* __restrict__ o4 = (const float4*)out;
        float acc = 0.0f;
#pragma unroll
        for (int k = 0; k < DWORK; k++) {
            const int idx   = t + k * (DB * 256);          // 0 .. 393215
            const int plane = idx >> 12;                   // 0..95  (b*3 + a)
            const int j     = idx & 4095;
            const int b     = plane / 3;
            const int a     = plane - 3 * b;
            float4 v = o4[(size_t)(b * NCH + a * 6 + 4) * 4096 + j];
            acc += softplus_fast(v.x) + softplus_fast(v.y)
                 + softplus_fast(v.z) + softplus_fast(v.w);
        }
        double ds = warp_reduce_d((double)acc);
        if (lane == 0) sredD[wid] = ds;
        __syncthreads();
        if (wid == 0) {
            double s = (lane < 8) ? sredD[lane] : 0.0;
#pragma unroll
            for (int o = 4; o > 0; o >>= 1) s += __shfl_down_sync(0xffu, s, o);
            if (lane == 0) atomicAdd(&d_total, s);         // non-returning -> RED
        }
        return;
    }

    // ---------------- GT phase: one (gt, anchor) pair per thread --------------
    const unsigned int gen = d_gen + 1;   // stable for the whole launch
    const float stride_h = (float)((*size_h) / NH);
    const float stride_w = (float)((*size_w) / NW);
    float awf[3], ahf[3];
#pragma unroll
    for (int a = 0; a < 3; a++) { awf[a] = c_aw[a] / stride_w; ahf[a] = c_ah[a] / stride_h; }

    const int pair = bid * 256 + tid;                      // 0 .. 3*nGts-1
    double corr = 0.0, objsum = 0.0;
    int nclr = 0, nobj = 0;
    if (pair < 3 * nGts) {
        const int g = pair / 3;
        const int a = pair - 3 * g;
        const int b = gt_batch[g];
        float4 box = ((const float4*)gt_boxes)[g];
        float gx = box.x * (float)NW, gy = box.y * (float)NH;
        float gw = box.z * (float)NW, gh = box.w * (float)NH;
        int gi = (int)gx, gj = (int)gy;

        float ious[3];
        int bestn = best_anchor(gw, gh, awf, ahf, ious);
        const bool isbest  = (a == bestn);
        const bool cleared = (ious[a] > 0.5f) || isbest;

        if (cleared) {
            const int cell = ((b * NA + a) * NH + gj) * NW + gi;
            const unsigned long long newv =
                ((unsigned long long)gen << 32) | (isbest ? (unsigned)(g + 1) : 0u);
            unsigned long long old = atomicMax(&d_tag[cell], newv);
            const unsigned int old_gen = (unsigned int)(old >> 32);
            const unsigned int old_g   = (unsigned int)old;   // g+1 of prior owner (this gen)
            const bool first = (old_gen < gen);

            if (first) {   // first toucher of this cell this launch -> noobj correction
                float v = out[(size_t)(b * NCH + a * 6 + 4) * NPLANE + gj * NW + gi];
                corr += (double)bce_neg(v);
                nclr++;
            }
            if (isbest) {
                const unsigned int prior = first ? 0u : old_g;
                if (prior < (unsigned)(g + 1)) {   // we became the (transient) owner
                    objsum += obj_term(out, b, bestn, gi, gj, gx, gy, gw, gh,
                                       awf[bestn], ahf[bestn]);
                    if (prior == 0u) {
                        nobj++;
                    } else {
                        // displaced gt prior-1 maps to the SAME cell
                        float4 obox = ((const float4*)gt_boxes)[prior - 1];
                        float ogx = obox.x * (float)NW, ogy = obox.y * (float)NH;
                        float ogw = obox.z * (float)NW, ogh = obox.w * (float)NH;
                        objsum -= obj_term(out, b, bestn, gi, gj, ogx, ogy, ogw, ogh,
                                           awf[bestn], ahf[bestn]);
                    }
                }
            }
        }
    }

    double dsC = warp_reduce_d(corr);
    double dsO = warp_reduce_d(objsum);
    int    isC = warp_reduce_i(nclr);
    int    isO = warp_reduce_i(nobj);
    if (lane == 0) { sredD[wid] = dsC; sredI[wid] = isC; }
    __syncthreads();
    if (wid == 0) {
        double s = (lane < 8) ? sredD[lane] : 0.0;
        int    n = (lane < 8) ? sredI[lane] : 0;
#pragma unroll
        for (int o = 4; o > 0; o >>= 1) {
            s += __shfl_down_sync(0xffu, s, o);
            n += __shfl_down_sync(0xffu, n, o);
        }
        if (lane == 0 && n > 0) { atomicAdd(&d_corr, s); atomicAdd(&d_nclr, n); }
    }
    __syncthreads();
    if (lane == 0) { sredD[wid] = dsO; sredI[wid] = isO; }
    __syncthreads();
    if (wid == 0) {
        double s = (lane < 8) ? sredD[lane] : 0.0;
        int    n = (lane < 8) ? sredI[lane] : 0;
#pragma unroll
        for (int o = 4; o > 0; o >>= 1) {
            s += __shfl_down_sync(0xffu, s, o);
            n += __shfl_down_sync(0xffu, n, o);
        }
        if (lane == 0) {
            if (s != 0.0) atomicAdd(&d_obj, s);
            if (n > 0)    atomicAdd(&d_nobj, n);
        }
    }
}

// ---------------------------------------------------------------------------
// K2: ONE tiny block, launched with programmatic stream serialization so its
// prologue overlaps K1. cudaGridDependencySynchronize() waits for K1's full
// completion (all RED accumulator writes visible), then finalize + reset.
// ---------------------------------------------------------------------------
__global__ void k2_finalize(float* __restrict__ d_out) {
    cudaGridDependencySynchronize();   // wait for K1 grid completion
    if (threadIdx.x == 0) {
        double total = d_total;
        double corr  = d_corr;
        double obj   = d_obj;
        int    no    = d_nobj;
        int    ncl   = d_nclr;
        double n_obj  = (double)(no > 0 ? no : 1);
        int    nno    = NCELL - ncl;
        double n_noob = (double)(nno > 0 ? nno : 1);
        d_out[0] = (float)(obj / n_obj + 100.0 * (total - corr) / n_noob);
        // reset accumulators; bump gen -> all d_tag entries become stale
        d_total = 0.0; d_corr = 0.0; d_obj = 0.0;
        d_nclr = 0; d_nobj = 0;
        d_gen = d_gen + 1;
    }
}

extern "C" void kernel_launch(void* const* d_in, const int* in_sizes, int n_in,
                              void* d_out, int out_size) {
    const float* out      = (const float*)d_in[0];
    const int*   gt_batch = (const int*)  d_in[1];
    const float* gt_boxes = (const float*)d_in[2];
    const int*   size_h   = (const int*)  d_in[3];
    const int*   size_w   = (const int*)  d_in[4];
    float* outp = (float*)d_out;
    const int nGts = in_sizes[1];

    const int gtABlocks = (3 * nGts + 255) / 256;   // 23 for nGts=1920
    k1_dense_gt<<<gtABlocks + DB, 256>>>(out, gt_batch, gt_boxes,
                                         size_h, size_w, nGts, gtABlocks);

    // K2 with programmatic dependent launch: prologue overlaps K1.
    cudaLaunchConfig_t cfg = {};
    cfg.gridDim  = dim3(1, 1, 1);
    cfg.blockDim = dim3(32, 1, 1);
    cudaLaunchAttribute attr[1];
    attr[0].id = cudaLaunchAttributeProgrammaticStreamSerialization;
    attr[0].val.programmaticStreamSerializationAllowed = 1;
    cfg.attrs = attr;
    cfg.numAttrs = 1;
    cudaLaunchKernelEx(&cfg, k2_finalize, outp);
}